// round 4
// baseline (speedup 1.0000x reference)
#include <cuda_runtime.h>

#define NT 512
#define TS 24
typedef unsigned long long u64;

// inter-layer activations: [t][j][v_global], 24*64*16384 floats = 100.7 MB
__device__ float g_act[TS * 64 * 16384];
// precomputed input-gate sums (bih folded in): [t][g][v_global], 302 MB
__device__ float g_xg[TS * 192 * 16384];

// smem offsets (floats)
#define OFF_WH  0        // 12288: whh in phase B / wih in phase A / fcW (head, spills into XG0)
#define OFF_XG0 12288    // 12288: xg tile buf0; phase A: x pair tiles (2 x 4096)
#define OFF_XG1 24576    // 12288: xg tile buf1
#define OFF_HS  36864    // 4096  [j][v]
#define OFF_SR  40960    // 4096
#define OFF_SZ  45056    // 4096
#define OFF_SHN 49152    // 4096
#define OFF_VIN 53248    // 1536  [t][v]
#define OFF_BI  54784    // 192
#define OFF_BH  54976    // 192
#define OFF_W0  55168    // 192
#define SMEM_FLOATS 55360  // 221,440 B

static __device__ __forceinline__ u64 dup2(float v) {
    u64 r; asm("mov.b64 %0, {%1, %1};" : "=l"(r) : "f"(v)); return r;
}
static __device__ __forceinline__ void fma2(u64 &d, u64 a, u64 b) {
    asm("fma.rn.f32x2 %0, %1, %2, %0;" : "+l"(d) : "l"(a), "l"(b));
}
static __device__ __forceinline__ float fsig(float x) {
    float e = __expf(-x);
    return __fdividef(1.f, 1.f + e);
}
static __device__ __forceinline__ float ftanh(float x) {
    x = fminf(fmaxf(x, -10.f), 10.f);
    float e = __expf(-2.f * x);
    return __fdividef(1.f - e, 1.f + e);
}

// ---- Phase A: XG[t] = Wih @ x_t + bih for all t, 2 timesteps per iteration ----
static __device__ void phaseA(float* __restrict__ sm, int tid, int vbase)
{
    const int lane = tid & 31, w = tid >> 5;
    const int v0 = lane * 2, gR = w * 4;
    const float* wi = sm + OFF_WH;
    const float* bi = sm + OFF_BI;
    float* XT = sm + OFF_XG0;                 // [half][k][v], 2 x 4096

    for (int p = 0; p < 12; ++p) {
        const int t0 = 2 * p;
        float4 pf[4];
        if (p < 11) {
            #pragma unroll
            for (int jj = 0; jj < 4; ++jj) {
                int q = tid + jj * NT;        // 0..2047 -> 8192 floats
                int tt = t0 + 2 + (q >> 10);
                int k  = (q >> 4) & 63;
                int v4 = (q & 15) << 2;
                pf[jj] = *(const float4*)&g_act[((tt * 64 + k) << 14) + vbase + v4];
            }
        }
        u64 a0[12], a1[12];
        #pragma unroll
        for (int i = 0; i < 4; ++i) {
            a0[i]     = dup2(bi[gR + i]);
            a0[4 + i] = dup2(bi[64 + gR + i]);
            a0[8 + i] = dup2(bi[128 + gR + i]);
            a1[i] = a0[i]; a1[4 + i] = a0[4 + i]; a1[8 + i] = a0[8 + i];
        }
        for (int k = 0; k < 64; k += 4) {
            u64 x0[4], x1[4];
            #pragma unroll
            for (int kk = 0; kk < 4; ++kk) {
                x0[kk] = *(const u64*)(XT + (k + kk) * 64 + v0);
                x1[kk] = *(const u64*)(XT + 4096 + (k + kk) * 64 + v0);
            }
            #pragma unroll
            for (int gsel = 0; gsel < 3; ++gsel) {
                float4 W[4];
                #pragma unroll
                for (int i = 0; i < 4; ++i)
                    W[i] = *(const float4*)(wi + (gsel * 64 + gR + i) * 64 + k);
                #pragma unroll
                for (int kk = 0; kk < 4; ++kk) {
                    #pragma unroll
                    for (int i = 0; i < 4; ++i) {
                        float wv = kk == 0 ? W[i].x : kk == 1 ? W[i].y
                                 : kk == 2 ? W[i].z : W[i].w;
                        u64 w2 = dup2(wv);
                        fma2(a0[gsel * 4 + i], x0[kk], w2);
                        fma2(a1[gsel * 4 + i], x1[kk], w2);
                    }
                }
            }
        }
        #pragma unroll
        for (int gsel = 0; gsel < 3; ++gsel) {
            #pragma unroll
            for (int i = 0; i < 4; ++i) {
                int g = gsel * 64 + gR + i;
                *(u64*)&g_xg[((t0 * 192 + g) << 14) + vbase + v0]       = a0[gsel * 4 + i];
                *(u64*)&g_xg[(((t0 + 1) * 192 + g) << 14) + vbase + v0] = a1[gsel * 4 + i];
            }
        }
        __syncthreads();
        if (p < 11) {
            #pragma unroll
            for (int jj = 0; jj < 4; ++jj) {
                int q = tid + jj * NT;
                int half = q >> 10;
                int k  = (q >> 4) & 63;
                int v4 = (q & 15) << 2;
                *(float4*)(XT + half * 4096 + k * 64 + v4) = pf[jj];
            }
        }
        __syncthreads();
    }
}

// ---- Phase B: recurrent hh matvec + combine; xg tiles prefetched from global ----
template<bool L0>
static __device__ void phaseB(float* __restrict__ sm, int tid, int vbase)
{
    const int lane = tid & 31, w = tid >> 5;
    const int v0 = lane * 2, gR = w * 4;
    const float* wh  = sm + OFF_WH;
    float*       hS  = sm + OFF_HS;
    const float* bh  = sm + OFF_BH;
    const float* bi  = sm + OFF_BI;
    const float* w0  = sm + OFF_W0;
    const float* vin = sm + OFF_VIN;

    for (int t = 0; t < TS; ++t) {
        const float* xgc = sm + OFF_XG0 + (t & 1) * 12288;
        float*       xgn = sm + OFF_XG0 + ((t + 1) & 1) * 12288;

        float4 pf[6];
        if (!L0 && t + 1 < TS) {
            #pragma unroll
            for (int jj = 0; jj < 6; ++jj) {
                int q = tid + jj * NT;        // 0..3071 -> 12288 floats
                int g = q >> 4, v4 = (q & 15) << 2;
                pf[jj] = *(const float4*)&g_xg[(((t + 1) * 192 + g) << 14) + vbase + v4];
            }
        }

        u64 aR[4], aZ[4], aN[4];
        #pragma unroll
        for (int i = 0; i < 4; ++i) {
            aR[i] = dup2(bh[gR + i]);
            aZ[i] = dup2(bh[64 + gR + i]);
            aN[i] = dup2(bh[128 + gR + i]);
        }
        for (int k = 0; k < 64; k += 4) {
            u64 h2[4];
            #pragma unroll
            for (int kk = 0; kk < 4; ++kk)
                h2[kk] = *(const u64*)(hS + (k + kk) * 64 + v0);
            #pragma unroll
            for (int gsel = 0; gsel < 3; ++gsel) {
                float4 W[4];
                #pragma unroll
                for (int i = 0; i < 4; ++i)
                    W[i] = *(const float4*)(wh + (gsel * 64 + gR + i) * 64 + k);
                #pragma unroll
                for (int kk = 0; kk < 4; ++kk) {
                    #pragma unroll
                    for (int i = 0; i < 4; ++i) {
                        float wv = kk == 0 ? W[i].x : kk == 1 ? W[i].y
                                 : kk == 2 ? W[i].z : W[i].w;
                        u64 w2 = dup2(wv);
                        u64* acc = gsel == 0 ? aR : gsel == 1 ? aZ : aN;
                        fma2(acc[i], h2[kk], w2);
                    }
                }
            }
        }
        #pragma unroll
        for (int i = 0; i < 4; ++i) {
            *(u64*)(sm + OFF_SR  + (gR + i) * 64 + v0) = aR[i];
            *(u64*)(sm + OFF_SZ  + (gR + i) * 64 + v0) = aZ[i];
            *(u64*)(sm + OFF_SHN + (gR + i) * 64 + v0) = aN[i];
        }
        if (!L0 && t + 1 < TS) {
            #pragma unroll
            for (int jj = 0; jj < 6; ++jj) {
                int q = tid + jj * NT;
                int g = q >> 4, v4 = (q & 15) << 2;
                *(float4*)(xgn + g * 64 + v4) = pf[jj];
            }
        }
        __syncthreads();

        #pragma unroll
        for (int it = 0; it < 8; ++it) {
            int idx = tid + it * NT, v = idx & 63, j = idx >> 6;
            float xr, xz, xn;
            if (L0) {
                float xv = vin[t * 64 + v];
                xr = xv * w0[j]        + bi[j];
                xz = xv * w0[64 + j]   + bi[64 + j];
                xn = xv * w0[128 + j]  + bi[128 + j];
            } else {
                xr = xgc[j * 64 + v];
                xz = xgc[(64 + j) * 64 + v];
                xn = xgc[(128 + j) * 64 + v];
            }
            float r = fsig(sm[OFF_SR + j * 64 + v] + xr);
            float z = fsig(sm[OFF_SZ + j * 64 + v] + xz);
            float n = ftanh(xn + r * sm[OFF_SHN + j * 64 + v]);
            float h = hS[j * 64 + v];
            h = (1.f - z) * n + z * h;
            hS[j * 64 + v] = h;
            g_act[((t * 64 + j) << 14) + vbase + v] = h;
        }
        __syncthreads();
    }
}

__global__ void __launch_bounds__(NT, 1)
fused_rnn_kernel(const float* __restrict__ x,   const int*   __restrict__ lengths,
                 const float* __restrict__ sf,  const float* __restrict__ bp,
                 const float* __restrict__ wih0,const float* __restrict__ whh0,
                 const float* __restrict__ bih0,const float* __restrict__ bhh0,
                 const float* __restrict__ wihL,const float* __restrict__ whhL,
                 const float* __restrict__ bihL,const float* __restrict__ bhhL,
                 const float* __restrict__ bng, const float* __restrict__ bnb,
                 const float* __restrict__ bnm, const float* __restrict__ bnv,
                 const float* __restrict__ fcW, const float* __restrict__ fcb,
                 const float* __restrict__ fcWo,const float* __restrict__ fcbo,
                 float* __restrict__ out)
{
    extern __shared__ float sm[];
    const int tid = threadIdx.x;
    const int vbase = blockIdx.x * 64;
    const int n  = vbase >> 12;
    const int sb = vbase & 4095;

    // scaled scalar input sequences vin[t][v]
    for (int idx = tid; idx < TS * 64; idx += NT) {
        int t = idx >> 6, v = idx & 63;
        int p = t % 3;
        sm[OFF_VIN + idx] = x[n * 98304 + t * 4096 + sb + v] * sf[p] + bp[p];
    }

    // ---- layer 0 (ih is rank-1, done inline in combine) ----
    for (int idx = tid; idx < 12288; idx += NT) sm[OFF_WH + idx] = whh0[idx];
    if (tid < 192) {
        sm[OFF_BI + tid] = bih0[tid];
        sm[OFF_BH + tid] = bhh0[tid];
        sm[OFF_W0 + tid] = wih0[tid];
    }
    for (int idx = tid; idx < 4096; idx += NT) sm[OFF_HS + idx] = 0.f;
    __syncthreads();
    phaseB<true>(sm, tid, vbase);

    // ---- layers 1..3: phase A (ih GEMM) then phase B (recurrence) ----
    for (int l = 1; l < 4; ++l) {
        __syncthreads();
        const float* Wi = wihL + (l - 1) * 12288;
        for (int idx = tid; idx < 12288; idx += NT) sm[OFF_WH + idx] = Wi[idx];
        if (tid < 192) sm[OFF_BI + tid] = bihL[(l - 1) * 192 + tid];
        #pragma unroll
        for (int jj = 0; jj < 4; ++jj) {          // stage x pair (t=0,1)
            int q = tid + jj * NT;
            int tt = q >> 10, k = (q >> 4) & 63, v4 = (q & 15) << 2;
            *(float4*)(sm + OFF_XG0 + tt * 4096 + k * 64 + v4) =
                *(const float4*)&g_act[((tt * 64 + k) << 14) + vbase + v4];
        }
        __syncthreads();
        phaseA(sm, tid, vbase);

        __syncthreads();
        const float* Wh = whhL + (l - 1) * 12288;
        for (int idx = tid; idx < 12288; idx += NT) sm[OFF_WH + idx] = Wh[idx];
        if (tid < 192) sm[OFF_BH + tid] = bhhL[(l - 1) * 192 + tid];
        for (int idx = tid; idx < 4096; idx += NT) sm[OFF_HS + idx] = 0.f;
        #pragma unroll
        for (int jj = 0; jj < 6; ++jj) {          // stage xg tile t=0
            int q = tid + jj * NT;
            int g = q >> 4, v4 = (q & 15) << 2;
            *(float4*)(sm + OFF_XG0 + g * 64 + v4) =
                *(const float4*)&g_xg[(g << 14) + vbase + v4];
        }
        __syncthreads();
        phaseB<false>(sm, tid, vbase);
    }

    // ---- head: sel = h[len-1]+h[len-4]; 5x (BN+SiLU+FC); BN+SiLU; out ----
    __syncthreads();
    for (int idx = tid; idx < 20480; idx += NT) sm[OFF_WH + idx] = fcW[idx];
    float* A = sm + OFF_SR;
    float* B = sm + OFF_SZ;
    const int len = lengths[n];
    const int t1 = len - 1, t2 = len - 4;
    #pragma unroll
    for (int it = 0; it < 8; ++it) {
        int idx = tid + it * NT, v = idx & 63, j = idx >> 6;
        A[j * 64 + v] = g_act[((t1 * 64 + j) << 14) + vbase + v]
                      + g_act[((t2 * 64 + j) << 14) + vbase + v];
    }
    __syncthreads();
    for (int i = 0; i < 5; ++i) {
        #pragma unroll
        for (int it = 0; it < 8; ++it) {
            int idx = tid + it * NT, v = idx & 63, j = idx >> 6;
            float y = bng[i * 64 + j] * (A[j * 64 + v] - bnm[i * 64 + j])
                      * rsqrtf(bnv[i * 64 + j] + 1e-5f) + bnb[i * 64 + j];
            A[j * 64 + v] = y * fsig(y);
        }
        __syncthreads();
        const float* Wl = sm + OFF_WH + i * 4096;
        #pragma unroll
        for (int it = 0; it < 8; ++it) {
            int idx = tid + it * NT, v = idx & 63, o = idx >> 6;
            float acc = fcb[i * 64 + o];
            #pragma unroll 8
            for (int j = 0; j < 64; ++j) acc += A[j * 64 + v] * Wl[o * 64 + j];
            B[o * 64 + v] = acc;
        }
        __syncthreads();
        float* tswp = A; A = B; B = tswp;
    }
    #pragma unroll
    for (int it = 0; it < 8; ++it) {
        int idx = tid + it * NT, v = idx & 63, j = idx >> 6;
        float y = bng[5 * 64 + j] * (A[j * 64 + v] - bnm[5 * 64 + j])
                  * rsqrtf(bnv[5 * 64 + j] + 1e-5f) + bnb[5 * 64 + j];
        A[j * 64 + v] = y * fsig(y);
    }
    __syncthreads();
    if (tid < 64) {
        float acc = fcbo[0];
        #pragma unroll 8
        for (int j = 0; j < 64; ++j) acc += A[j * 64 + tid] * fcWo[j];
        out[vbase + tid] = acc;
    }
}

extern "C" void kernel_launch(void* const* d_in, const int* in_sizes, int n_in,
                              void* d_out, int out_size)
{
    const float* x     = (const float*)d_in[0];
    const int*   lens  = (const int*)  d_in[1];
    const float* sf    = (const float*)d_in[2];
    const float* bp    = (const float*)d_in[3];
    const float* wih0  = (const float*)d_in[4];
    const float* whh0  = (const float*)d_in[5];
    const float* bih0  = (const float*)d_in[6];
    const float* bhh0  = (const float*)d_in[7];
    const float* wihL  = (const float*)d_in[8];
    const float* whhL  = (const float*)d_in[9];
    const float* bihL  = (const float*)d_in[10];
    const float* bhhL  = (const float*)d_in[11];
    const float* bng   = (const float*)d_in[12];
    const float* bnb   = (const float*)d_in[13];
    const float* bnm   = (const float*)d_in[14];
    const float* bnv   = (const float*)d_in[15];
    const float* fcW   = (const float*)d_in[16];
    const float* fcb   = (const float*)d_in[17];
    const float* fcWo  = (const float*)d_in[18];
    const float* fcbo  = (const float*)d_in[19];
    float* out = (float*)d_out;

    const size_t smem = SMEM_FLOATS * sizeof(float);  // 221,440 B
    cudaFuncSetAttribute(fused_rnn_kernel,
                         cudaFuncAttributeMaxDynamicSharedMemorySize, (int)smem);
    fused_rnn_kernel<<<256, NT, smem>>>(
        x, lens, sf, bp, wih0, whh0, bih0, bhh0,
        wihL, whhL, bihL, bhhL, bng, bnb, bnm, bnv,
        fcW, fcb, fcWo, fcbo, out);
}

// round 5
// speedup vs baseline: 1.3700x; 1.3700x over previous
#include <cuda_runtime.h>
#include <cstdint>

#define NT 512
#define VB 128          // voxels per block
#define TS 24
typedef unsigned long long u64;

// inter-layer activations: [t][j][v_global], 24*64*16384 floats = 100.7 MB
__device__ float g_act[TS * 64 * 16384];

// smem offsets (floats)
#define OFF_WI  0        // 12288
#define OFF_WH  12288    // 12288
#define OFF_XC  24576    // 8192  x tile [k][v]
#define OFF_HS  32768    // 8192  h state [j][v]
#define OFF_VIN 40960    // 3072  [t][v]
#define OFF_BI  44032    // 192
#define OFF_BH  44224    // 192
#define OFF_W0  44416    // 192
#define SMEM_FLOATS 44608   // 178,432 B

static __device__ __forceinline__ u64 pk2(float lo, float hi) {
    u64 r; asm("mov.b64 %0, {%1, %2};" : "=l"(r) : "f"(lo), "f"(hi)); return r;
}
static __device__ __forceinline__ void upk2(u64 v, float &lo, float &hi) {
    asm("mov.b64 {%0, %1}, %2;" : "=f"(lo), "=f"(hi) : "l"(v));
}
static __device__ __forceinline__ u64 dup2(float v) {
    u64 r; asm("mov.b64 %0, {%1, %1};" : "=l"(r) : "f"(v)); return r;
}
static __device__ __forceinline__ void fma2(u64 &d, u64 a, u64 b) {
    asm("fma.rn.f32x2 %0, %1, %2, %0;" : "+l"(d) : "l"(a), "l"(b));
}
static __device__ __forceinline__ float tanha(float x) {
    float y; asm("tanh.approx.f32 %0, %1;" : "=f"(y) : "f"(x)); return y;
}
static __device__ __forceinline__ float sigt(float x) {   // sigmoid via tanh
    return fmaf(tanha(0.5f * x), 0.5f, 0.5f);
}
static __device__ __forceinline__ void cpa16(uint32_t dst, const void* src) {
    asm volatile("cp.async.ca.shared.global [%0], [%1], 16;\n" :: "r"(dst), "l"(src));
}

// One GRU layer over all T steps.
// warp w owns gates {4w..4w+3} of each of r/z/n; lane owns voxels {4l..4l+3}.
// Combine is thread-local (same j for r/z/n lives in the same thread).
template<bool L0>
static __device__ void layer_steps(float* __restrict__ sm, int tid, int vbase)
{
    const int lane = tid & 31, w = tid >> 5;
    const int v0 = lane * 4, gRb = w * 4;
    const float* wh  = sm + OFF_WH;
    const float* wi  = sm + OFF_WI;
    float*       hS  = sm + OFF_HS;
    const float* bi  = sm + OFF_BI;
    const float* bh  = sm + OFF_BH;
    const float* w0  = sm + OFF_W0;
    const float* vin = sm + OFF_VIN;
    float*       xc  = sm + OFF_XC;
    const uint32_t xc_s = (uint32_t)__cvta_generic_to_shared(xc);

    for (int t = 0; t < TS; ++t) {
        u64 aR[8], aZ[8], aNH[8], aNX[8];
        #pragma unroll
        for (int i = 0; i < 4; ++i) {
            int g = gRb + i;
            float vR = bh[g]        + (L0 ? 0.f : bi[g]);
            float vZ = bh[64 + g]   + (L0 ? 0.f : bi[64 + g]);
            float vH = bh[128 + g];
            float vX = L0 ? 0.f : bi[128 + g];
            aR[2*i] = dup2(vR);  aR[2*i+1] = dup2(vR);
            aZ[2*i] = dup2(vZ);  aZ[2*i+1] = dup2(vZ);
            aNH[2*i] = dup2(vH); aNH[2*i+1] = dup2(vH);
            aNX[2*i] = dup2(vX); aNX[2*i+1] = dup2(vX);
        }

        for (int k = 0; k < 64; k += 4) {
            u64 h2[8], x2[8];
            #pragma unroll
            for (int kk = 0; kk < 4; ++kk) {
                float4 hv = *(const float4*)(hS + (k + kk) * VB + v0);
                h2[2*kk] = pk2(hv.x, hv.y); h2[2*kk+1] = pk2(hv.z, hv.w);
                if (!L0) {
                    float4 xv = *(const float4*)(xc + (k + kk) * VB + v0);
                    x2[2*kk] = pk2(xv.x, xv.y); x2[2*kk+1] = pk2(xv.z, xv.w);
                }
            }
            #pragma unroll
            for (int gs = 0; gs < 3; ++gs) {
                u64* acc = (gs == 0) ? aR : (gs == 1) ? aZ : aNH;
                float4 W[4];
                #pragma unroll
                for (int i = 0; i < 4; ++i)
                    W[i] = *(const float4*)(wh + (gs * 64 + gRb + i) * 64 + k);
                #pragma unroll
                for (int kk = 0; kk < 4; ++kk) {
                    #pragma unroll
                    for (int i = 0; i < 4; ++i) {
                        float wv = kk == 0 ? W[i].x : kk == 1 ? W[i].y
                                 : kk == 2 ? W[i].z : W[i].w;
                        u64 w2 = dup2(wv);
                        fma2(acc[2*i],   h2[2*kk],   w2);
                        fma2(acc[2*i+1], h2[2*kk+1], w2);
                    }
                }
            }
            if (!L0) {
                #pragma unroll
                for (int gs = 0; gs < 3; ++gs) {
                    u64* acc = (gs == 0) ? aR : (gs == 1) ? aZ : aNX;
                    float4 W[4];
                    #pragma unroll
                    for (int i = 0; i < 4; ++i)
                        W[i] = *(const float4*)(wi + (gs * 64 + gRb + i) * 64 + k);
                    #pragma unroll
                    for (int kk = 0; kk < 4; ++kk) {
                        #pragma unroll
                        for (int i = 0; i < 4; ++i) {
                            float wv = kk == 0 ? W[i].x : kk == 1 ? W[i].y
                                     : kk == 2 ? W[i].z : W[i].w;
                            u64 w2 = dup2(wv);
                            fma2(acc[2*i],   x2[2*kk],   w2);
                            fma2(acc[2*i+1], x2[2*kk+1], w2);
                        }
                    }
                }
            }
        }
        __syncthreads();   // barrier1: all matvec reads of hS/xc complete

        // refill x tile for t+1 (in place) via cp.async, hidden under combine
        if (!L0 && t + 1 < TS) {
            #pragma unroll
            for (int jj = 0; jj < 4; ++jj) {
                int q = tid + jj * NT;
                int k = q >> 5, v4 = (q & 31) << 2;
                cpa16(xc_s + (uint32_t)((k * VB + v4) * 4),
                      &g_act[(((t + 1) * 64 + k) << 14) + vbase + v4]);
            }
            asm volatile("cp.async.commit_group;\n" ::: "memory");
        }

        // thread-local combine + h write
        #pragma unroll
        for (int i = 0; i < 4; ++i) {
            int g = gRb + i;
            float rr[4], zz[4], qx[4], qh[4];
            upk2(aR[2*i],  rr[0], rr[1]); upk2(aR[2*i+1],  rr[2], rr[3]);
            upk2(aZ[2*i],  zz[0], zz[1]); upk2(aZ[2*i+1],  zz[2], zz[3]);
            upk2(aNH[2*i], qh[0], qh[1]); upk2(aNH[2*i+1], qh[2], qh[3]);
            if (!L0) { upk2(aNX[2*i], qx[0], qx[1]); upk2(aNX[2*i+1], qx[2], qx[3]); }
            if (L0) {
                float4 vv = *(const float4*)(vin + t * VB + v0);
                float xs[4] = {vv.x, vv.y, vv.z, vv.w};
                float wr = w0[g], wz = w0[64 + g], wn = w0[128 + g];
                float br = bi[g], bz = bi[64 + g], bn = bi[128 + g];
                #pragma unroll
                for (int u = 0; u < 4; ++u) {
                    rr[u] += xs[u] * wr + br;
                    zz[u] += xs[u] * wz + bz;
                    qx[u]  = xs[u] * wn + bn;
                }
            }
            float4 ho = *(const float4*)(hS + g * VB + v0);
            float hol[4] = {ho.x, ho.y, ho.z, ho.w};
            float hn[4];
            #pragma unroll
            for (int u = 0; u < 4; ++u) {
                float r  = sigt(rr[u]);
                float z  = sigt(zz[u]);
                float nn = tanha(qx[u] + r * qh[u]);
                hn[u] = (1.f - z) * nn + z * hol[u];
            }
            float4 res = make_float4(hn[0], hn[1], hn[2], hn[3]);
            *(float4*)(hS + g * VB + v0) = res;
            *(float4*)&g_act[((t * 64 + g) << 14) + vbase + v0] = res;
        }
        if (!L0 && t + 1 < TS)
            asm volatile("cp.async.wait_group 0;\n" ::: "memory");
        __syncthreads();   // barrier2: h/x updates visible
    }
}

__global__ void __launch_bounds__(NT)
fused_rnn_kernel(const float* __restrict__ x,   const int*   __restrict__ lengths,
                 const float* __restrict__ sf,  const float* __restrict__ bp,
                 const float* __restrict__ wih0,const float* __restrict__ whh0,
                 const float* __restrict__ bih0,const float* __restrict__ bhh0,
                 const float* __restrict__ wihL,const float* __restrict__ whhL,
                 const float* __restrict__ bihL,const float* __restrict__ bhhL,
                 const float* __restrict__ bng, const float* __restrict__ bnb,
                 const float* __restrict__ bnm, const float* __restrict__ bnv,
                 const float* __restrict__ fcW, const float* __restrict__ fcb,
                 const float* __restrict__ fcWo,const float* __restrict__ fcbo,
                 float* __restrict__ out)
{
    extern __shared__ float sm[];
    const int tid = threadIdx.x;
    const int vbase = blockIdx.x * VB;
    const int n  = vbase >> 12;
    const int sb = vbase & 4095;

    // scaled scalar input sequences vin[t][v]
    for (int idx = tid; idx < TS * VB; idx += NT) {
        int t = idx >> 7, v = idx & 127;
        int p = t % 3;
        sm[OFF_VIN + idx] = x[n * 98304 + t * 4096 + sb + v] * sf[p] + bp[p];
    }

    for (int l = 0; l < 4; ++l) {
        if (l == 0) {
            for (int idx = tid; idx < 12288; idx += NT) sm[OFF_WH + idx] = whh0[idx];
            if (tid < 192) {
                sm[OFF_BI + tid] = bih0[tid];
                sm[OFF_BH + tid] = bhh0[tid];
                sm[OFF_W0 + tid] = wih0[tid];
            }
        } else {
            const float* Wi = wihL + (l - 1) * 12288;
            const float* Wh = whhL + (l - 1) * 12288;
            for (int idx = tid; idx < 12288; idx += NT) {
                sm[OFF_WI + idx] = Wi[idx];
                sm[OFF_WH + idx] = Wh[idx];
            }
            if (tid < 192) {
                sm[OFF_BI + tid] = bihL[(l - 1) * 192 + tid];
                sm[OFF_BH + tid] = bhhL[(l - 1) * 192 + tid];
            }
            // stage x tile (t=0)
            #pragma unroll
            for (int jj = 0; jj < 4; ++jj) {
                int q = tid + jj * NT;
                int k = q >> 5, v4 = (q & 31) << 2;
                *(float4*)(sm + OFF_XC + k * VB + v4) =
                    *(const float4*)&g_act[(k << 14) + vbase + v4];
            }
        }
        for (int idx = tid; idx < 8192; idx += NT) sm[OFF_HS + idx] = 0.f;
        __syncthreads();
        if (l == 0) layer_steps<true >(sm, tid, vbase);
        else        layer_steps<false>(sm, tid, vbase);
    }

    // ---- head: sel = h[len-1]+h[len-4]; 5x (BN+SiLU+FC); BN+SiLU; out ----
    for (int idx = tid; idx < 20480; idx += NT) sm[OFF_WI + idx] = fcW[idx];
    float* A = sm + OFF_XC;    // [j][v] 64x128
    float* B = sm + OFF_HS;
    const int len = lengths[n];
    const int t1 = len - 1, t2 = len - 4;
    #pragma unroll
    for (int it = 0; it < 16; ++it) {
        int idx = tid + it * NT, v = idx & 127, j = idx >> 7;
        A[j * VB + v] = g_act[((t1 * 64 + j) << 14) + vbase + v]
                      + g_act[((t2 * 64 + j) << 14) + vbase + v];
    }
    __syncthreads();
    for (int i = 0; i < 5; ++i) {
        #pragma unroll
        for (int it = 0; it < 16; ++it) {
            int idx = tid + it * NT, v = idx & 127, j = idx >> 7;
            float y = bng[i * 64 + j] * (A[j * VB + v] - bnm[i * 64 + j])
                      * rsqrtf(bnv[i * 64 + j] + 1e-5f) + bnb[i * 64 + j];
            A[j * VB + v] = y * sigt(y);
        }
        __syncthreads();
        const float* Wl = sm + OFF_WI + i * 4096;
        #pragma unroll
        for (int it = 0; it < 16; ++it) {
            int idx = tid + it * NT, v = idx & 127, o = idx >> 7;
            float acc = fcb[i * 64 + o];
            #pragma unroll 8
            for (int j = 0; j < 64; ++j) acc += A[j * VB + v] * Wl[o * 64 + j];
            B[o * VB + v] = acc;
        }
        __syncthreads();
        float* tswp = A; A = B; B = tswp;
    }
    #pragma unroll
    for (int it = 0; it < 16; ++it) {
        int idx = tid + it * NT, v = idx & 127, j = idx >> 7;
        float y = bng[5 * 64 + j] * (A[j * VB + v] - bnm[5 * 64 + j])
                  * rsqrtf(bnv[5 * 64 + j] + 1e-5f) + bnb[5 * 64 + j];
        A[j * VB + v] = y * sigt(y);
    }
    __syncthreads();
    if (tid < VB) {
        float acc = fcbo[0];
        #pragma unroll 8
        for (int j = 0; j < 64; ++j) acc += A[j * VB + tid] * fcWo[j];
        out[vbase + tid] = acc;
    }
}

extern "C" void kernel_launch(void* const* d_in, const int* in_sizes, int n_in,
                              void* d_out, int out_size)
{
    const float* x     = (const float*)d_in[0];
    const int*   lens  = (const int*)  d_in[1];
    const float* sf    = (const float*)d_in[2];
    const float* bp    = (const float*)d_in[3];
    const float* wih0  = (const float*)d_in[4];
    const float* whh0  = (const float*)d_in[5];
    const float* bih0  = (const float*)d_in[6];
    const float* bhh0  = (const float*)d_in[7];
    const float* wihL  = (const float*)d_in[8];
    const float* whhL  = (const float*)d_in[9];
    const float* bihL  = (const float*)d_in[10];
    const float* bhhL  = (const float*)d_in[11];
    const float* bng   = (const float*)d_in[12];
    const float* bnb   = (const float*)d_in[13];
    const float* bnm   = (const float*)d_in[14];
    const float* bnv   = (const float*)d_in[15];
    const float* fcW   = (const float*)d_in[16];
    const float* fcb   = (const float*)d_in[17];
    const float* fcWo  = (const float*)d_in[18];
    const float* fcbo  = (const float*)d_in[19];
    float* out = (float*)d_out;

    const size_t smem = SMEM_FLOATS * sizeof(float);  // 178,432 B
    cudaFuncSetAttribute(fused_rnn_kernel,
                         cudaFuncAttributeMaxDynamicSharedMemorySize, (int)smem);
    fused_rnn_kernel<<<128, NT, smem>>>(
        x, lens, sf, bp, wih0, whh0, bih0, bhh0,
        wihL, whhL, bihL, bhhL, bng, bnb, bnm, bnv,
        fcW, fcb, fcWo, fcbo, out);
}

// round 6
// speedup vs baseline: 1.4159x; 1.0335x over previous
#include <cuda_runtime.h>
#include <cstdint>

#define NT 512
#define VB 128          // voxels per block
#define TS 24
typedef unsigned long long u64;

// inter-layer activations: [t][j][v_global], 24*64*16384 floats = 100.7 MB
__device__ float g_act[TS * 64 * 16384];

// smem offsets (floats) — double-buffered x and h
#define OFF_WI   0        // 12288
#define OFF_WH   12288    // 12288
#define OFF_XC0  24576    // 8192  x tile buf0 [k][v]   (VIN overlays here during L0)
#define OFF_XC1  32768    // 8192  x tile buf1
#define OFF_HS0  40960    // 8192  h state buf0 [j][v]
#define OFF_HS1  49152    // 8192  h state buf1
#define OFF_BI   57344    // 192
#define OFF_BH   57536    // 192
#define OFF_W0   57728    // 192
#define SMEM_FLOATS 57920 // 231,680 B  (<= 232,448 B limit)
#define OFF_VIN  OFF_XC0  // [t][v], 3072 floats, live only in layer 0

static __device__ __forceinline__ u64 dup2(float v) {
    u64 r; asm("mov.b64 %0, {%1, %1};" : "=l"(r) : "f"(v)); return r;
}
static __device__ __forceinline__ void upk2(u64 v, float &lo, float &hi) {
    asm("mov.b64 {%0, %1}, %2;" : "=f"(lo), "=f"(hi) : "l"(v));
}
static __device__ __forceinline__ void fma2(u64 &d, u64 a, u64 b) {
    asm("fma.rn.f32x2 %0, %1, %2, %0;" : "+l"(d) : "l"(a), "l"(b));
}
static __device__ __forceinline__ float tanha(float x) {
    float y; asm("tanh.approx.f32 %0, %1;" : "=f"(y) : "f"(x)); return y;
}
static __device__ __forceinline__ float sigt(float x) {   // sigmoid via tanh
    return fmaf(tanha(0.5f * x), 0.5f, 0.5f);
}
static __device__ __forceinline__ void cpa16(uint32_t dst, const void* src) {
    asm volatile("cp.async.ca.shared.global [%0], [%1], 16;\n" :: "r"(dst), "l"(src));
}

// One GRU layer over all T steps.
// warp w owns gates {4w..4w+3} of each of r/z/n; lane owns voxels {4l..4l+3}.
// h and x double-buffered: ONE barrier per step; x[next] refilled via cp.async
// issued at step start (covered by the whole step).
template<bool L0>
static __device__ void layer_steps(float* __restrict__ sm, int tid, int vbase)
{
    const int lane = tid & 31, w = tid >> 5;
    const int v0 = lane * 4, gRb = w * 4;
    const float* wh  = sm + OFF_WH;
    const float* wi  = sm + OFF_WI;
    const float* bi  = sm + OFF_BI;
    const float* bh  = sm + OFF_BH;
    const float* w0  = sm + OFF_W0;
    const float* vin = sm + OFF_VIN;
    const uint32_t xc0_s = (uint32_t)__cvta_generic_to_shared(sm + OFF_XC0);
    const uint32_t xc1_s = (uint32_t)__cvta_generic_to_shared(sm + OFF_XC1);

    for (int t = 0; t < TS; ++t) {
        const float* hc = sm + ((t & 1) ? OFF_HS1 : OFF_HS0);
        float*       hn = sm + ((t & 1) ? OFF_HS0 : OFF_HS1);
        const float* xc = sm + ((t & 1) ? OFF_XC1 : OFF_XC0);
        const uint32_t xn_s = (t & 1) ? xc0_s : xc1_s;

        // refill x[next] for t+1 — issued first, lands during this whole step
        if (!L0 && t + 1 < TS) {
            #pragma unroll
            for (int jj = 0; jj < 4; ++jj) {
                int q = tid + jj * NT;
                int k = q >> 5, v4 = (q & 31) << 2;
                cpa16(xn_s + (uint32_t)((k * VB + v4) * 4),
                      &g_act[(((t + 1) * 64 + k) << 14) + vbase + v4]);
            }
            asm volatile("cp.async.commit_group;\n" ::: "memory");
        }

        u64 aR[8], aZ[8], aNH[8], aNX[8];
        #pragma unroll
        for (int i = 0; i < 4; ++i) {
            int g = gRb + i;
            float vR = bh[g]        + (L0 ? 0.f : bi[g]);
            float vZ = bh[64 + g]   + (L0 ? 0.f : bi[64 + g]);
            float vH = bh[128 + g];
            float vX = L0 ? 0.f : bi[128 + g];
            aR[2*i] = dup2(vR);  aR[2*i+1] = dup2(vR);
            aZ[2*i] = dup2(vZ);  aZ[2*i+1] = dup2(vZ);
            aNH[2*i] = dup2(vH); aNH[2*i+1] = dup2(vH);
            aNX[2*i] = dup2(vX); aNX[2*i+1] = dup2(vX);
        }

        for (int k = 0; k < 64; k += 4) {
            u64 h2[8], x2[8];
            #pragma unroll
            for (int kk = 0; kk < 4; ++kk) {
                ulonglong2 hv = *(const ulonglong2*)(hc + (k + kk) * VB + v0);
                h2[2*kk] = hv.x; h2[2*kk+1] = hv.y;
                if (!L0) {
                    ulonglong2 xv = *(const ulonglong2*)(xc + (k + kk) * VB + v0);
                    x2[2*kk] = xv.x; x2[2*kk+1] = xv.y;
                }
            }
            #pragma unroll
            for (int gs = 0; gs < 3; ++gs) {
                u64* acc = (gs == 0) ? aR : (gs == 1) ? aZ : aNH;
                float4 W[4];
                #pragma unroll
                for (int i = 0; i < 4; ++i)
                    W[i] = *(const float4*)(wh + (gs * 64 + gRb + i) * 64 + k);
                #pragma unroll
                for (int kk = 0; kk < 4; ++kk) {
                    #pragma unroll
                    for (int i = 0; i < 4; ++i) {
                        float wv = kk == 0 ? W[i].x : kk == 1 ? W[i].y
                                 : kk == 2 ? W[i].z : W[i].w;
                        u64 w2 = dup2(wv);
                        fma2(acc[2*i],   h2[2*kk],   w2);
                        fma2(acc[2*i+1], h2[2*kk+1], w2);
                    }
                }
            }
            if (!L0) {
                #pragma unroll
                for (int gs = 0; gs < 3; ++gs) {
                    u64* acc = (gs == 0) ? aR : (gs == 1) ? aZ : aNX;
                    float4 W[4];
                    #pragma unroll
                    for (int i = 0; i < 4; ++i)
                        W[i] = *(const float4*)(wi + (gs * 64 + gRb + i) * 64 + k);
                    #pragma unroll
                    for (int kk = 0; kk < 4; ++kk) {
                        #pragma unroll
                        for (int i = 0; i < 4; ++i) {
                            float wv = kk == 0 ? W[i].x : kk == 1 ? W[i].y
                                     : kk == 2 ? W[i].z : W[i].w;
                            u64 w2 = dup2(wv);
                            fma2(acc[2*i],   x2[2*kk],   w2);
                            fma2(acc[2*i+1], x2[2*kk+1], w2);
                        }
                    }
                }
            }
        }

        // thread-local combine: reads old h (hc), writes new h (hn) — no barrier needed
        #pragma unroll
        for (int i = 0; i < 4; ++i) {
            int g = gRb + i;
            float rr[4], zz[4], qx[4], qh[4];
            upk2(aR[2*i],  rr[0], rr[1]); upk2(aR[2*i+1],  rr[2], rr[3]);
            upk2(aZ[2*i],  zz[0], zz[1]); upk2(aZ[2*i+1],  zz[2], zz[3]);
            upk2(aNH[2*i], qh[0], qh[1]); upk2(aNH[2*i+1], qh[2], qh[3]);
            if (!L0) { upk2(aNX[2*i], qx[0], qx[1]); upk2(aNX[2*i+1], qx[2], qx[3]); }
            if (L0) {
                float4 vv = *(const float4*)(vin + t * VB + v0);
                float xs[4] = {vv.x, vv.y, vv.z, vv.w};
                float wr = w0[g], wz = w0[64 + g], wn = w0[128 + g];
                float br = bi[g], bz = bi[64 + g], bn = bi[128 + g];
                #pragma unroll
                for (int u = 0; u < 4; ++u) {
                    rr[u] += xs[u] * wr + br;
                    zz[u] += xs[u] * wz + bz;
                    qx[u]  = xs[u] * wn + bn;
                }
            }
            float4 ho = *(const float4*)(hc + g * VB + v0);
            float hol[4] = {ho.x, ho.y, ho.z, ho.w};
            float hv[4];
            #pragma unroll
            for (int u = 0; u < 4; ++u) {
                float r  = sigt(rr[u]);
                float z  = sigt(zz[u]);
                float nn = tanha(qx[u] + r * qh[u]);
                hv[u] = (1.f - z) * nn + z * hol[u];
            }
            float4 res = make_float4(hv[0], hv[1], hv[2], hv[3]);
            *(float4*)(hn + g * VB + v0) = res;
            *(float4*)&g_act[((t * 64 + g) << 14) + vbase + v0] = res;
        }
        if (!L0 && t + 1 < TS)
            asm volatile("cp.async.wait_group 0;\n" ::: "memory");
        __syncthreads();   // single barrier per step
    }
}

__global__ void __launch_bounds__(NT)
fused_rnn_kernel(const float* __restrict__ x,   const int*   __restrict__ lengths,
                 const float* __restrict__ sf,  const float* __restrict__ bp,
                 const float* __restrict__ wih0,const float* __restrict__ whh0,
                 const float* __restrict__ bih0,const float* __restrict__ bhh0,
                 const float* __restrict__ wihL,const float* __restrict__ whhL,
                 const float* __restrict__ bihL,const float* __restrict__ bhhL,
                 const float* __restrict__ bng, const float* __restrict__ bnb,
                 const float* __restrict__ bnm, const float* __restrict__ bnv,
                 const float* __restrict__ fcW, const float* __restrict__ fcb,
                 const float* __restrict__ fcWo,const float* __restrict__ fcbo,
                 float* __restrict__ out)
{
    extern __shared__ float sm[];
    const int tid = threadIdx.x;
    const int vbase = blockIdx.x * VB;
    const int n  = vbase >> 12;
    const int sb = vbase & 4095;

    // scaled scalar input sequences vin[t][v] (overlaid on XC0; used only in L0)
    for (int idx = tid; idx < TS * VB; idx += NT) {
        int t = idx >> 7, v = idx & 127;
        int p = t % 3;
        sm[OFF_VIN + idx] = x[n * 98304 + t * 4096 + sb + v] * sf[p] + bp[p];
    }

    for (int l = 0; l < 4; ++l) {
        if (l == 0) {
            for (int idx = tid; idx < 12288; idx += NT) sm[OFF_WH + idx] = whh0[idx];
            if (tid < 192) {
                sm[OFF_BI + tid] = bih0[tid];
                sm[OFF_BH + tid] = bhh0[tid];
                sm[OFF_W0 + tid] = wih0[tid];
            }
        } else {
            const float* Wi = wihL + (l - 1) * 12288;
            const float* Wh = whhL + (l - 1) * 12288;
            for (int idx = tid; idx < 12288; idx += NT) {
                sm[OFF_WI + idx] = Wi[idx];
                sm[OFF_WH + idx] = Wh[idx];
            }
            if (tid < 192) {
                sm[OFF_BI + tid] = bihL[(l - 1) * 192 + tid];
                sm[OFF_BH + tid] = bhhL[(l - 1) * 192 + tid];
            }
            // stage x tile t=0 into XC0 (overwrites VIN after L0 — safe)
            #pragma unroll
            for (int jj = 0; jj < 4; ++jj) {
                int q = tid + jj * NT;
                int k = q >> 5, v4 = (q & 31) << 2;
                *(float4*)(sm + OFF_XC0 + k * VB + v4) =
                    *(const float4*)&g_act[(k << 14) + vbase + v4];
            }
        }
        for (int idx = tid; idx < 8192; idx += NT) sm[OFF_HS0 + idx] = 0.f;
        __syncthreads();
        if (l == 0) layer_steps<true >(sm, tid, vbase);
        else        layer_steps<false>(sm, tid, vbase);
    }

    // ---- head: sel = h[len-1]+h[len-4]; 5x (BN+SiLU+FC); BN+SiLU; out ----
    for (int idx = tid; idx < 20480; idx += NT) sm[OFF_WI + idx] = fcW[idx];
    float* A = sm + OFF_XC0;    // [j][v] 64x128
    float* B = sm + OFF_XC1;
    const int len = lengths[n];
    const int t1 = len - 1, t2 = len - 4;
    #pragma unroll
    for (int it = 0; it < 16; ++it) {
        int idx = tid + it * NT, v = idx & 127, j = idx >> 7;
        A[j * VB + v] = g_act[((t1 * 64 + j) << 14) + vbase + v]
                      + g_act[((t2 * 64 + j) << 14) + vbase + v];
    }
    __syncthreads();
    for (int i = 0; i < 5; ++i) {
        #pragma unroll
        for (int it = 0; it < 16; ++it) {
            int idx = tid + it * NT, v = idx & 127, j = idx >> 7;
            float y = bng[i * 64 + j] * (A[j * VB + v] - bnm[i * 64 + j])
                      * rsqrtf(bnv[i * 64 + j] + 1e-5f) + bnb[i * 64 + j];
            A[j * VB + v] = y * sigt(y);
        }
        __syncthreads();
        const float* Wl = sm + OFF_WI + i * 4096;
        #pragma unroll
        for (int it = 0; it < 16; ++it) {
            int idx = tid + it * NT, v = idx & 127, o = idx >> 7;
            float acc = fcb[i * 64 + o];
            #pragma unroll 8
            for (int j = 0; j < 64; ++j) acc += A[j * VB + v] * Wl[o * 64 + j];
            B[o * VB + v] = acc;
        }
        __syncthreads();
        float* tswp = A; A = B; B = tswp;
    }
    #pragma unroll
    for (int it = 0; it < 16; ++it) {
        int idx = tid + it * NT, v = idx & 127, j = idx >> 7;
        float y = bng[5 * 64 + j] * (A[j * VB + v] - bnm[5 * 64 + j])
                  * rsqrtf(bnv[5 * 64 + j] + 1e-5f) + bnb[5 * 64 + j];
        A[j * VB + v] = y * sigt(y);
    }
    __syncthreads();
    if (tid < VB) {
        float acc = fcbo[0];
        #pragma unroll 8
        for (int j = 0; j < 64; ++j) acc += A[j * VB + tid] * fcWo[j];
        out[vbase + tid] = acc;
    }
}

extern "C" void kernel_launch(void* const* d_in, const int* in_sizes, int n_in,
                              void* d_out, int out_size)
{
    const float* x     = (const float*)d_in[0];
    const int*   lens  = (const int*)  d_in[1];
    const float* sf    = (const float*)d_in[2];
    const float* bp    = (const float*)d_in[3];
    const float* wih0  = (const float*)d_in[4];
    const float* whh0  = (const float*)d_in[5];
    const float* bih0  = (const float*)d_in[6];
    const float* bhh0  = (const float*)d_in[7];
    const float* wihL  = (const float*)d_in[8];
    const float* whhL  = (const float*)d_in[9];
    const float* bihL  = (const float*)d_in[10];
    const float* bhhL  = (const float*)d_in[11];
    const float* bng   = (const float*)d_in[12];
    const float* bnb   = (const float*)d_in[13];
    const float* bnm   = (const float*)d_in[14];
    const float* bnv   = (const float*)d_in[15];
    const float* fcW   = (const float*)d_in[16];
    const float* fcb   = (const float*)d_in[17];
    const float* fcWo  = (const float*)d_in[18];
    const float* fcbo  = (const float*)d_in[19];
    float* out = (float*)d_out;

    const size_t smem = SMEM_FLOATS * sizeof(float);  // 231,680 B
    cudaFuncSetAttribute(fused_rnn_kernel,
                         cudaFuncAttributeMaxDynamicSharedMemorySize, (int)smem);
    fused_rnn_kernel<<<128, NT, smem>>>(
        x, lens, sf, bp, wih0, whh0, bih0, bhh0,
        wihL, whhL, bihL, bhhL, bng, bnb, bnm, bnv,
        fcW, fcb, fcWo, fcbo, out);
}

// round 8
// speedup vs baseline: 3.8644x; 2.7294x over previous
#include <cuda_runtime.h>
#include <cstdint>

#define NT 512
#define VB 128
#define TS 24

// inter-layer activations, A-frag-major: [t][blk][mt(8)][kt(8)][lane(32)][q(4)]
__device__ float g_act[TS * 128 * 8192];

// ---- smem float offsets ----
#define S_WH 0        // 12288: Whh B-frags (tf32 bits)
#define S_WI 12288    // 12288: Wih B-frags (VIN overlays here during L0)
#define S_H0 24576    // 8192: h A-frag buf0
#define S_H1 32768
#define S_X0 40960    // 8192: x A-frag buf0
#define S_X1 49152
#define S_BS 57344    // 256: biases per (type,j): r=bi+bh, z=bi+bh, nh=bh, ni=bi
#define S_W0 57600    // 192: layer-0 rank-1 ih weights (fp32)
#define SMEM_FLOATS 57792   // 231,168 B
#define S_VIN S_WI

static __device__ __forceinline__ uint32_t tf32b(float f) {
    uint32_t r; asm("cvt.rna.tf32.f32 %0, %1;" : "=r"(r) : "f"(f)); return r;
}
static __device__ __forceinline__ float tanha(float x) {
    float y; asm("tanh.approx.f32 %0, %1;" : "=f"(y) : "f"(x)); return y;
}
static __device__ __forceinline__ float sigt(float x) {
    return fmaf(tanha(0.5f * x), 0.5f, 0.5f);
}
static __device__ __forceinline__ void cpa16(uint32_t dst, const void* src) {
    asm volatile("cp.async.ca.shared.global [%0], [%1], 16;\n" :: "r"(dst), "l"(src));
}
// D(16x8) += A(16x8,row,tf32) * B(8x8,col,tf32), fp32 accumulate
#define MMA(c, a, b) asm volatile( \
    "mma.sync.aligned.m16n8k8.row.col.f32.tf32.tf32.f32 " \
    "{%0,%1,%2,%3},{%4,%5,%6,%7},{%8,%9},{%0,%1,%2,%3};" \
    : "+f"((c)[0]), "+f"((c)[1]), "+f"((c)[2]), "+f"((c)[3]) \
    : "r"((a).x), "r"((a).y), "r"((a).z), "r"((a).w), "r"((b).x), "r"((b).y))

// One GRU layer, 24 steps. Warp w: mg=w&3 (voxels 32mg..32mg+32), ng=w>>2 (j 16ng..16ng+16).
// C frags: r/z accumulate hh+ih; n kept as separate hh and ih frags.
template<bool L0>
static __device__ void layer_run(float* __restrict__ sm, int tid, int blk)
{
    const int lane = tid & 31, w = tid >> 5;
    const int mg = w & 3, ng = w >> 2;
    const int gq = lane >> 2, cc = lane & 3;
    const uint32_t* WH = (const uint32_t*)(sm + S_WH);
    const uint32_t* WI = (const uint32_t*)(sm + S_WI);
    const float* BS = sm + S_BS;

    for (int t = 0; t < TS; ++t) {
        float*       hb_n = sm + ((t & 1) ? S_H0 : S_H1);
        const float* hb_c = sm + ((t & 1) ? S_H1 : S_H0);
        const uint32_t* XC = (const uint32_t*)(sm + ((t & 1) ? S_X1 : S_X0));
        const uint32_t xn_s = (uint32_t)__cvta_generic_to_shared(
                                  sm + ((t & 1) ? S_X0 : S_X1));

        if (!L0 && t + 1 < TS) {   // prefetch x[t+1] (frag layout = plain 16B chunks)
            const float* src = &g_act[((size_t)((t + 1) * 128 + blk)) << 13];
            #pragma unroll
            for (int jj = 0; jj < 4; ++jj) {
                int q = tid + jj * NT;
                cpa16(xn_s + (uint32_t)(q * 16), src + q * 4);
            }
            asm volatile("cp.async.commit_group;\n" ::: "memory");
        }

        float cr[4][4], cz[4][4], cnh[4][4], cnx[4][4];
        #pragma unroll
        for (int f = 0; f < 4; ++f)
            #pragma unroll
            for (int q = 0; q < 4; ++q) {
                cr[f][q] = 0.f; cz[f][q] = 0.f; cnh[f][q] = 0.f; cnx[f][q] = 0.f;
            }

        const uint32_t* HB = (const uint32_t*)hb_c;
        #pragma unroll 2
        for (int kt = 0; kt < 8; ++kt) {
            uint2 bhr[2], bhz[2], bhn[2], bir[2], biz[2], bin[2];
            #pragma unroll
            for (int ji = 0; ji < 2; ++ji) {
                int jt = 2 * ng + ji;
                bhr[ji] = *(const uint2*)(WH + ((jt)      * 8 + kt) * 64 + lane * 2);
                bhz[ji] = *(const uint2*)(WH + ((8 + jt)  * 8 + kt) * 64 + lane * 2);
                bhn[ji] = *(const uint2*)(WH + ((16 + jt) * 8 + kt) * 64 + lane * 2);
                if (!L0) {
                    bir[ji] = *(const uint2*)(WI + ((jt)      * 8 + kt) * 64 + lane * 2);
                    biz[ji] = *(const uint2*)(WI + ((8 + jt)  * 8 + kt) * 64 + lane * 2);
                    bin[ji] = *(const uint2*)(WI + ((16 + jt) * 8 + kt) * 64 + lane * 2);
                }
            }
            #pragma unroll
            for (int mi = 0; mi < 2; ++mi) {
                int mt = 2 * mg + mi;
                uint4 ah, ax;
                if (t > 0) ah = *(const uint4*)(HB + mt * 1024 + kt * 128 + lane * 4);
                if (!L0)   ax = *(const uint4*)(XC + mt * 1024 + kt * 128 + lane * 4);
                #pragma unroll
                for (int ji = 0; ji < 2; ++ji) {
                    int f = mi * 2 + ji;
                    if (t > 0) {
                        MMA(cr[f],  ah, bhr[ji]);
                        MMA(cz[f],  ah, bhz[ji]);
                        MMA(cnh[f], ah, bhn[ji]);
                    }
                    if (!L0) {
                        MMA(cr[f],  ax, bir[ji]);
                        MMA(cz[f],  ax, biz[ji]);
                        MMA(cnx[f], ax, bin[ji]);
                    }
                }
            }
        }

        // thread-local combine (all 4 gate sums of (v,j) live here)
        #pragma unroll
        for (int mi = 0; mi < 2; ++mi) {
            int mt = 2 * mg + mi;
            #pragma unroll
            for (int ji = 0; ji < 2; ++ji) {
                int jt = 2 * ng + ji, f = mi * 2 + ji;
                float*       hrow = hb_n + (mt * 8 + jt) * 128;
                const float* hold = hb_c + (mt * 8 + jt) * 128;
                #pragma unroll
                for (int d = 0; d < 2; ++d) {
                    int j = jt * 8 + cc * 2 + d;
                    float br = BS[j], bz = BS[64 + j];
                    float bnh = BS[128 + j], bni = BS[192 + j];
                    int tp4 = gq * 16 + ((2 * cc + d) & 3) * 4;
                    int qb  = (cc >= 2) ? 2 : 0;
                    float hpair[2];
                    #pragma unroll
                    for (int b = 0; b < 2; ++b) {
                        int q = 2 * b + d;
                        float xr = 0.f, xz = 0.f, xn;
                        if (L0) {
                            int v = mt * 16 + gq + 8 * b;
                            float xv = sm[S_VIN + t * VB + v];
                            xr = xv * sm[S_W0 + j];
                            xz = xv * sm[S_W0 + 64 + j];
                            xn = xv * sm[S_W0 + 128 + j] + bni;
                        } else {
                            xn = cnx[f][q] + bni;
                        }
                        float hp = (t > 0) ? hold[tp4 + qb + b] : 0.f;
                        float r  = sigt(cr[f][q] + xr + br);
                        float z  = sigt(cz[f][q] + xz + bz);
                        float nn = tanha(xn + r * (cnh[f][q] + bnh));
                        hpair[b] = (1.f - z) * nn + z * hp;
                    }
                    *(float2*)(hrow + tp4 + qb) = make_float2(
                        __uint_as_float(tf32b(hpair[0])),
                        __uint_as_float(tf32b(hpair[1])));
                }
            }
        }
        if (!L0 && t + 1 < TS)
            asm volatile("cp.async.wait_group 0;\n" ::: "memory");
        __syncthreads();

        // coalesced copy of new h to g_act (read-read with next step's mma)
        {
            float* dst = &g_act[((size_t)(t * 128 + blk)) << 13];
            #pragma unroll
            for (int i = 0; i < 4; ++i) {
                int q = tid + i * NT;
                *(float4*)(dst + q * 4) = *(const float4*)(hb_n + q * 4);
            }
        }
    }
}

__global__ void __launch_bounds__(NT)
fused_rnn_kernel(const float* __restrict__ x,   const int*   __restrict__ lengths,
                 const float* __restrict__ sf,  const float* __restrict__ bp,
                 const float* __restrict__ wih0,const float* __restrict__ whh0,
                 const float* __restrict__ bih0,const float* __restrict__ bhh0,
                 const float* __restrict__ wihL,const float* __restrict__ whhL,
                 const float* __restrict__ bihL,const float* __restrict__ bhhL,
                 const float* __restrict__ bng, const float* __restrict__ bnb,
                 const float* __restrict__ bnm, const float* __restrict__ bnv,
                 const float* __restrict__ fcW, const float* __restrict__ fcb,
                 const float* __restrict__ fcWo,const float* __restrict__ fcbo,
                 float* __restrict__ out)
{
    extern __shared__ float sm[];
    const int tid = threadIdx.x;
    const int blk = blockIdx.x;
    const int vbase = blk * VB;
    const int n  = vbase >> 12;
    const int sb = vbase & 4095;

    for (int l = 0; l < 4; ++l) {
        const float* Wh = (l == 0) ? whh0 : whhL + (l - 1) * 12288;
        const float* Wi = (l == 0) ? wih0 : wihL + (l - 1) * 12288;
        const float* Bi = (l == 0) ? bih0 : bihL + (l - 1) * 192;
        const float* Bh = (l == 0) ? bhh0 : bhhL + (l - 1) * 192;
        // stage weight B-frags (tf32 bits)
        for (int idx = tid; idx < 12288; idx += NT) {
            int g = idx >> 6, k = idx & 63;
            uint32_t a = (uint32_t)(((g >> 3) * 8 + (k >> 3)) * 64
                       + (g & 7) * 8 + (k & 3) * 2 + ((k >> 2) & 1));
            ((uint32_t*)(sm + S_WH))[a] = tf32b(Wh[idx]);
            if (l > 0) ((uint32_t*)(sm + S_WI))[a] = tf32b(Wi[idx]);
        }
        if (tid < 64) {   // fused biases per (type, j)
            int j = tid;
            sm[S_BS + j]        = Bi[j] + Bh[j];
            sm[S_BS + 64 + j]   = Bi[64 + j] + Bh[64 + j];
            sm[S_BS + 128 + j]  = Bh[128 + j];
            sm[S_BS + 192 + j]  = Bi[128 + j];
        }
        if (l == 0) {
            if (tid < 192) sm[S_W0 + tid] = wih0[tid];   // rank-1 ih weights (fp32)
            for (int idx = tid; idx < TS * VB; idx += NT) {   // vin[t][v]
                int t = idx >> 7, v = idx & 127;
                int p = t % 3;
                sm[S_VIN + idx] = x[n * 98304 + t * 4096 + sb + v] * sf[p] + bp[p];
            }
        } else {          // stage x(t=0) frag tile
            const float* src = &g_act[((size_t)blk) << 13];
            #pragma unroll
            for (int i = 0; i < 4; ++i) {
                int q = tid + i * NT;
                *(float4*)(sm + S_X0 + q * 4) = *(const float4*)(src + q * 4);
            }
        }
        __syncthreads();
        if (l == 0) layer_run<true >(sm, tid, blk);
        else        layer_run<false>(sm, tid, blk);
        __syncthreads();
    }

    // ---- head: sel = h[len-1]+h[len-4]; 5x (BN+SiLU+FC); BN+SiLU; out ----
    for (int idx = tid; idx < 20480; idx += NT) sm[S_WH + idx] = fcW[idx];
    float* A = sm + S_H0;    // [j][v] 64 x 128
    float* B = sm + S_H1;
    const int len = lengths[n];
    const int t1 = len - 1, t2 = len - 4;
    for (int idx = tid; idx < 8192; idx += NT) {
        int v = idx & 127, j = idx >> 7;
        size_t fo = (size_t)((v >> 4) * 1024 + (j >> 3) * 128
                  + ((v & 7) * 4 + (j & 3)) * 4 + ((j & 4) >> 1) + ((v & 8) >> 3));
        A[j * VB + v] = g_act[(((size_t)(t1 * 128 + blk)) << 13) + fo]
                      + g_act[(((size_t)(t2 * 128 + blk)) << 13) + fo];
    }
    __syncthreads();
    for (int i = 0; i < 5; ++i) {
        #pragma unroll
        for (int it = 0; it < 16; ++it) {
            int idx = tid + it * NT, v = idx & 127, j = idx >> 7;
            float y = bng[i * 64 + j] * (A[j * VB + v] - bnm[i * 64 + j])
                      * rsqrtf(bnv[i * 64 + j] + 1e-5f) + bnb[i * 64 + j];
            A[j * VB + v] = y * sigt(y);
        }
        __syncthreads();
        const float* Wl = sm + S_WH + i * 4096;
        #pragma unroll
        for (int it = 0; it < 16; ++it) {
            int idx = tid + it * NT, v = idx & 127, o = idx >> 7;
            float acc = fcb[i * 64 + o];
            #pragma unroll 8
            for (int j = 0; j < 64; ++j) acc += A[j * VB + v] * Wl[o * 64 + j];
            B[o * VB + v] = acc;
        }
        __syncthreads();
        float* tswp = A; A = B; B = tswp;
    }
    #pragma unroll
    for (int it = 0; it < 16; ++it) {
        int idx = tid + it * NT, v = idx & 127, j = idx >> 7;
        float y = bng[5 * 64 + j] * (A[j * VB + v] - bnm[5 * 64 + j])
                  * rsqrtf(bnv[5 * 64 + j] + 1e-5f) + bnb[5 * 64 + j];
        A[j * VB + v] = y * sigt(y);
    }
    __syncthreads();
    if (tid < VB) {
        float acc = fcbo[0];
        #pragma unroll 8
        for (int j = 0; j < 64; ++j) acc += A[j * VB + tid] * fcWo[j];
        out[vbase + tid] = acc;
    }
}

extern "C" void kernel_launch(void* const* d_in, const int* in_sizes, int n_in,
                              void* d_out, int out_size)
{
    const float* x     = (const float*)d_in[0];
    const int*   lens  = (const int*)  d_in[1];
    const float* sf    = (const float*)d_in[2];
    const float* bp    = (const float*)d_in[3];
    const float* wih0  = (const float*)d_in[4];
    const float* whh0  = (const float*)d_in[5];
    const float* bih0  = (const float*)d_in[6];
    const float* bhh0  = (const float*)d_in[7];
    const float* wihL  = (const float*)d_in[8];
    const float* whhL  = (const float*)d_in[9];
    const float* bihL  = (const float*)d_in[10];
    const float* bhhL  = (const float*)d_in[11];
    const float* bng   = (const float*)d_in[12];
    const float* bnb   = (const float*)d_in[13];
    const float* bnm   = (const float*)d_in[14];
    const float* bnv   = (const float*)d_in[15];
    const float* fcW   = (const float*)d_in[16];
    const float* fcb   = (const float*)d_in[17];
    const float* fcWo  = (const float*)d_in[18];
    const float* fcbo  = (const float*)d_in[19];
    float* out = (float*)d_out;

    const size_t smem = SMEM_FLOATS * sizeof(float);   // 231,168 B
    cudaFuncSetAttribute(fused_rnn_kernel,
                         cudaFuncAttributeMaxDynamicSharedMemorySize, (int)smem);
    fused_rnn_kernel<<<128, NT, smem>>>(
        x, lens, sf, bp, wih0, whh0, bih0, bhh0,
        wihL, whhL, bihL, bhhL, bng, bnb, bnm, bnv,
        fcW, fcb, fcWo, fcbo, out);
}

// round 9
// speedup vs baseline: 6.2488x; 1.6170x over previous
#include <cuda_runtime.h>
#include <cuda_bf16.h>
#include <cstdint>

#define NT 512
#define VB 128
#define TS 24

// layers 0-2 activations as bf16 A-frag tiles: [t][blk][1024 x uint4] = 48 MB
__device__ uint4 g_actb[TS * 128 * 1024];
// layer-3 output fp32, head layout [t][j][v_global] = 100 MB
__device__ float g_act2[TS * 64 * 16384];

// ---- smem float offsets ----
#define S_WH 0        // 6144 u32: Whh B-frags (bf16x2)
#define S_WI 6144     // 6144 u32: Wih B-frags (VIN overlays during L0)
#define S_H0 12288    // 4096 u32: h A-frags buf0
#define S_H1 16384
#define S_X0 20480    // 4096 u32: x A-frags buf0
#define S_X1 24576
#define S_BS 28672    // 256 fused biases
#define S_W0 28928    // 192 layer-0 rank-1 ih weights
#define SMEM_FLOATS 29120   // 116,480 B
#define S_VIN S_WI

static __device__ __forceinline__ uint32_t pkbf(float lo, float hi) {
    __nv_bfloat162 b = __float22bfloat162_rn(make_float2(lo, hi));  // .x = lo
    return *(uint32_t*)&b;
}
static __device__ __forceinline__ float tanha(float x) {
    float y; asm("tanh.approx.f32 %0, %1;" : "=f"(y) : "f"(x)); return y;
}
static __device__ __forceinline__ float sigt(float x) {
    return fmaf(tanha(0.5f * x), 0.5f, 0.5f);
}
static __device__ __forceinline__ void cpa16(uint32_t dst, const void* src) {
    asm volatile("cp.async.ca.shared.global [%0], [%1], 16;\n" :: "r"(dst), "l"(src));
}
// D(16x8,f32) += A(16x16 bf16 row) * B(16x8 bf16 col)
#define MMAB(c, a, b) asm volatile( \
    "mma.sync.aligned.m16n8k16.row.col.f32.bf16.bf16.f32 " \
    "{%0,%1,%2,%3},{%4,%5,%6,%7},{%8,%9},{%0,%1,%2,%3};" \
    : "+f"((c)[0]), "+f"((c)[1]), "+f"((c)[2]), "+f"((c)[3]) \
    : "r"((a).x), "r"((a).y), "r"((a).z), "r"((a).w), "r"((b).x), "r"((b).y))

// One GRU layer, 24 steps. Warp w: mg=w&3 (32 voxels), ng=w>>2 (16 j-cols).
// h_prev carried fp32 in registers; smem h/x are bf16 A-frags.
template<bool L0, bool LAST>
static __device__ void layer_run(float* __restrict__ sm, int tid, int blk)
{
    const int lane = tid & 31, w = tid >> 5;
    const int mg = w & 3, ng = w >> 2;
    const int gq = lane >> 2, cc = lane & 3;
    const int vbase = blk * VB;
    const uint2* WHu = (const uint2*)(sm + S_WH);
    const uint2* WIu = (const uint2*)(sm + S_WI);
    const float* BS = sm + S_BS;
    float hp[16];
    #pragma unroll
    for (int i = 0; i < 16; ++i) hp[i] = 0.f;

    for (int t = 0; t < TS; ++t) {
        uint4*       hb_n = (uint4*)(sm + ((t & 1) ? S_H0 : S_H1));
        const uint4* hb_c = (const uint4*)(sm + ((t & 1) ? S_H1 : S_H0));
        const uint4* XC   = (const uint4*)(sm + ((t & 1) ? S_X1 : S_X0));
        const uint32_t xn_s = (uint32_t)__cvta_generic_to_shared(
                                  sm + ((t & 1) ? S_X0 : S_X1));

        if (!L0 && t + 1 < TS) {   // prefetch x[t+1] frag tile (16 KB)
            const uint4* src = &g_actb[(size_t)((t + 1) * 128 + blk) * 1024];
            #pragma unroll
            for (int jj = 0; jj < 2; ++jj) {
                int q = tid + jj * NT;
                cpa16(xn_s + (uint32_t)(q * 16), src + q);
            }
            asm volatile("cp.async.commit_group;\n" ::: "memory");
        }

        float cr[4][4], cz[4][4], cnh[4][4], cnx[4][4];
        #pragma unroll
        for (int f = 0; f < 4; ++f)
            #pragma unroll
            for (int q = 0; q < 4; ++q) {
                cr[f][q] = 0.f; cz[f][q] = 0.f; cnh[f][q] = 0.f; cnx[f][q] = 0.f;
            }

        #pragma unroll
        for (int kt2 = 0; kt2 < 4; ++kt2) {
            uint2 bh[6], bi2[6];
            #pragma unroll
            for (int ji = 0; ji < 2; ++ji) {
                int jt = 2 * ng + ji;
                bh[ji*3+0] = WHu[((jt)      * 4 + kt2) * 32 + lane];
                bh[ji*3+1] = WHu[((8 + jt)  * 4 + kt2) * 32 + lane];
                bh[ji*3+2] = WHu[((16 + jt) * 4 + kt2) * 32 + lane];
                if (!L0) {
                    bi2[ji*3+0] = WIu[((jt)      * 4 + kt2) * 32 + lane];
                    bi2[ji*3+1] = WIu[((8 + jt)  * 4 + kt2) * 32 + lane];
                    bi2[ji*3+2] = WIu[((16 + jt) * 4 + kt2) * 32 + lane];
                }
            }
            #pragma unroll
            for (int mi = 0; mi < 2; ++mi) {
                int mt = 2 * mg + mi;
                uint4 ah, ax;
                if (t > 0) ah = hb_c[(mt * 4 + kt2) * 32 + lane];
                if (!L0)   ax = XC  [(mt * 4 + kt2) * 32 + lane];
                #pragma unroll
                for (int ji = 0; ji < 2; ++ji) {
                    int f = mi * 2 + ji;
                    if (t > 0) {
                        MMAB(cr[f],  ah, bh[ji*3+0]);
                        MMAB(cz[f],  ah, bh[ji*3+1]);
                        MMAB(cnh[f], ah, bh[ji*3+2]);
                    }
                    if (!L0) {
                        MMAB(cr[f],  ax, bi2[ji*3+0]);
                        MMAB(cz[f],  ax, bi2[ji*3+1]);
                        MMAB(cnx[f], ax, bi2[ji*3+2]);
                    }
                }
            }
        }

        // thread-local combine; h packs straight into A-frag uint4
        #pragma unroll
        for (int mi = 0; mi < 2; ++mi) {
            int mt = 2 * mg + mi;
            uint32_t rg[4];
            #pragma unroll
            for (int ji = 0; ji < 2; ++ji) {
                int f = mi * 2 + ji;
                float hv[4];
                #pragma unroll
                for (int q = 0; q < 4; ++q) {
                    int j = 16 * ng + 8 * ji + 2 * cc + (q & 1);
                    int v = mt * 16 + gq + 8 * (q >> 1);
                    float xr = 0.f, xz = 0.f, xn;
                    if (L0) {
                        float xv = sm[S_VIN + t * VB + v];
                        xr = xv * sm[S_W0 + j];
                        xz = xv * sm[S_W0 + 64 + j];
                        xn = xv * sm[S_W0 + 128 + j] + BS[192 + j];
                    } else {
                        xn = cnx[f][q] + BS[192 + j];
                    }
                    float r  = sigt(cr[f][q] + xr + BS[j]);
                    float z  = sigt(cz[f][q] + xz + BS[64 + j]);
                    float nn = tanha(xn + r * (cnh[f][q] + BS[128 + j]));
                    float hnv = (1.f - z) * nn + z * hp[f * 4 + q];
                    hp[f * 4 + q] = hnv;
                    hv[q] = hnv;
                    if (LAST)
                        g_act2[((size_t)(t * 64 + j) << 14) + vbase + v] = hnv;
                }
                rg[ji * 2 + 0] = pkbf(hv[0], hv[1]);
                rg[ji * 2 + 1] = pkbf(hv[2], hv[3]);
            }
            uint4 u = make_uint4(rg[0], rg[1], rg[2], rg[3]);
            hb_n[(mt * 4 + ng) * 32 + lane] = u;
            if (!LAST)
                g_actb[(size_t)(t * 128 + blk) * 1024 + (mt * 4 + ng) * 32 + lane] = u;
        }
        if (!L0 && t + 1 < TS)
            asm volatile("cp.async.wait_group 0;\n" ::: "memory");
        __syncthreads();
    }
}

__global__ void __launch_bounds__(NT)
fused_rnn_kernel(const float* __restrict__ x,   const int*   __restrict__ lengths,
                 const float* __restrict__ sf,  const float* __restrict__ bp,
                 const float* __restrict__ wih0,const float* __restrict__ whh0,
                 const float* __restrict__ bih0,const float* __restrict__ bhh0,
                 const float* __restrict__ wihL,const float* __restrict__ whhL,
                 const float* __restrict__ bihL,const float* __restrict__ bhhL,
                 const float* __restrict__ bng, const float* __restrict__ bnb,
                 const float* __restrict__ bnm, const float* __restrict__ bnv,
                 const float* __restrict__ fcW, const float* __restrict__ fcb,
                 const float* __restrict__ fcWo,const float* __restrict__ fcbo,
                 float* __restrict__ out)
{
    extern __shared__ float sm[];
    const int tid = threadIdx.x;
    const int blk = blockIdx.x;
    const int vbase = blk * VB;
    const int n  = vbase >> 12;
    const int sb = vbase & 4095;

    for (int l = 0; l < 4; ++l) {
        const float* Wh = (l == 0) ? whh0 : whhL + (l - 1) * 12288;
        const float* Wi = (l == 0) ? wih0 : wihL + (l - 1) * 12288;
        const float* Bi = (l == 0) ? bih0 : bihL + (l - 1) * 192;
        const float* Bh = (l == 0) ? bhh0 : bhhL + (l - 1) * 192;
        // stage bf16 B-frags: [gt][kt2][lane][breg]
        uint32_t* WHu = (uint32_t*)(sm + S_WH);
        uint32_t* WIu = (uint32_t*)(sm + S_WI);
        for (int idx = tid; idx < 6144; idx += NT) {
            int gt = idx >> 8, kt2 = (idx >> 6) & 3, ln = (idx >> 1) & 31, br = idx & 1;
            int g = gt * 8 + (ln >> 2);
            int k = kt2 * 16 + (ln & 3) * 2 + br * 8;
            WHu[idx] = pkbf(Wh[g * 64 + k], Wh[g * 64 + k + 1]);
            if (l > 0) WIu[idx] = pkbf(Wi[g * 64 + k], Wi[g * 64 + k + 1]);
        }
        if (tid < 64) {
            int j = tid;
            sm[S_BS + j]       = Bi[j] + Bh[j];
            sm[S_BS + 64 + j]  = Bi[64 + j] + Bh[64 + j];
            sm[S_BS + 128 + j] = Bh[128 + j];
            sm[S_BS + 192 + j] = Bi[128 + j];
        }
        if (l == 0) {
            if (tid < 192) sm[S_W0 + tid] = wih0[tid];
            for (int idx = tid; idx < TS * VB; idx += NT) {   // vin[t][v]
                int t = idx >> 7, v = idx & 127;
                int p = t % 3;
                sm[S_VIN + idx] = x[n * 98304 + t * 4096 + sb + v] * sf[p] + bp[p];
            }
        } else {   // stage x(t=0) frag tile
            uint4* X0 = (uint4*)(sm + S_X0);
            #pragma unroll
            for (int jj = 0; jj < 2; ++jj) {
                int q = tid + jj * NT;
                X0[q] = g_actb[(size_t)blk * 1024 + q];
            }
        }
        __syncthreads();
        if      (l == 0) layer_run<true , false>(sm, tid, blk);
        else if (l == 3) layer_run<false, true >(sm, tid, blk);
        else             layer_run<false, false>(sm, tid, blk);
        __syncthreads();
    }

    // ---- head: sel = h[len-1]+h[len-4]; 5x (BN+SiLU+FC); BN+SiLU; out ----
    float* A = sm + S_H0;    // [j][v] 64 x 128 (= H0+H1)
    float* B = sm + S_X0;    // (= X0+X1)
    const int len = lengths[n];
    const int t1 = len - 1, t2 = len - 4;
    #pragma unroll
    for (int it = 0; it < 16; ++it) {
        int idx = tid + it * NT, v = idx & 127, j = idx >> 7;
        A[j * VB + v] = g_act2[((size_t)(t1 * 64 + j) << 14) + vbase + v]
                      + g_act2[((size_t)(t2 * 64 + j) << 14) + vbase + v];
    }
    __syncthreads();
    for (int i = 0; i < 5; ++i) {
        for (int idx = tid; idx < 4096; idx += NT) sm[S_WH + idx] = fcW[i * 4096 + idx];
        #pragma unroll
        for (int it = 0; it < 16; ++it) {
            int idx = tid + it * NT, v = idx & 127, j = idx >> 7;
            float y = bng[i * 64 + j] * (A[j * VB + v] - bnm[i * 64 + j])
                      * rsqrtf(bnv[i * 64 + j] + 1e-5f) + bnb[i * 64 + j];
            A[j * VB + v] = y * sigt(y);
        }
        __syncthreads();
        const float* Wl = sm + S_WH;
        #pragma unroll
        for (int it = 0; it < 16; ++it) {
            int idx = tid + it * NT, v = idx & 127, o = idx >> 7;
            float acc = fcb[i * 64 + o];
            #pragma unroll 8
            for (int j = 0; j < 64; ++j) acc += A[j * VB + v] * Wl[o * 64 + j];
            B[o * VB + v] = acc;
        }
        __syncthreads();
        float* tswp = A; A = B; B = tswp;
    }
    #pragma unroll
    for (int it = 0; it < 16; ++it) {
        int idx = tid + it * NT, v = idx & 127, j = idx >> 7;
        float y = bng[5 * 64 + j] * (A[j * VB + v] - bnm[5 * 64 + j])
                  * rsqrtf(bnv[5 * 64 + j] + 1e-5f) + bnb[5 * 64 + j];
        A[j * VB + v] = y * sigt(y);
    }
    __syncthreads();
    if (tid < VB) {
        float acc = fcbo[0];
        #pragma unroll 8
        for (int j = 0; j < 64; ++j) acc += A[j * VB + tid] * fcWo[j];
        out[vbase + tid] = acc;
    }
}

extern "C" void kernel_launch(void* const* d_in, const int* in_sizes, int n_in,
                              void* d_out, int out_size)
{
    const float* x     = (const float*)d_in[0];
    const int*   lens  = (const int*)  d_in[1];
    const float* sf    = (const float*)d_in[2];
    const float* bp    = (const float*)d_in[3];
    const float* wih0  = (const float*)d_in[4];
    const float* whh0  = (const float*)d_in[5];
    const float* bih0  = (const float*)d_in[6];
    const float* bhh0  = (const float*)d_in[7];
    const float* wihL  = (const float*)d_in[8];
    const float* whhL  = (const float*)d_in[9];
    const float* bihL  = (const float*)d_in[10];
    const float* bhhL  = (const float*)d_in[11];
    const float* bng   = (const float*)d_in[12];
    const float* bnb   = (const float*)d_in[13];
    const float* bnm   = (const float*)d_in[14];
    const float* bnv   = (const float*)d_in[15];
    const float* fcW   = (const float*)d_in[16];
    const float* fcb   = (const float*)d_in[17];
    const float* fcWo  = (const float*)d_in[18];
    const float* fcbo  = (const float*)d_in[19];
    float* out = (float*)d_out;

    const size_t smem = SMEM_FLOATS * sizeof(float);   // 116,480 B
    cudaFuncSetAttribute(fused_rnn_kernel,
                         cudaFuncAttributeMaxDynamicSharedMemorySize, (int)smem);
    fused_rnn_kernel<<<128, NT, smem>>>(
        x, lens, sf, bp, wih0, whh0, bih0, bhh0,
        wihL, whhL, bihL, bhhL, bng, bnb, bnm, bnv,
        fcW, fcb, fcWo, fcbo, out);
}

// round 10
// speedup vs baseline: 6.4369x; 1.0301x over previous
#include <cuda_runtime.h>
#include <cuda_bf16.h>
#include <cstdint>

#define NT 512
#define VB 128
#define TS 24

// layers 0-2 activations as bf16 A-frag tiles: [t][blk][1024 x uint4] = 48 MB
__device__ uint4 g_actb[TS * 128 * 1024];
// layer-3 output fp32, head layout [t][j][v_global] = 100 MB
__device__ float g_act2[TS * 64 * 16384];

// ---- smem float offsets ----
// weights: L0 WH @0 (6144); L1 WH@6144 WI@12288; L2 WH@18432 WI@24576; L3 WH@30720 WI@36864
#define S_H0  43008   // 4096 u32: h A-frags buf0 (regions disjoint per mg-group)
#define S_H1  47104
#define S_BS  51200   // 4 x 256 fused biases
#define S_W0  52224   // 192 layer-0 rank-1 ih weights
#define S_VIN 52416   // 3072 vin[t][v]
#define SMEM_FLOATS 55488   // 221,952 B

static __device__ __forceinline__ uint32_t pkbf(float lo, float hi) {
    __nv_bfloat162 b = __float22bfloat162_rn(make_float2(lo, hi));
    return *(uint32_t*)&b;
}
static __device__ __forceinline__ float tanha(float x) {
    float y; asm("tanh.approx.f32 %0, %1;" : "=f"(y) : "f"(x)); return y;
}
static __device__ __forceinline__ float sigt(float x) {
    return fmaf(tanha(0.5f * x), 0.5f, 0.5f);
}
#define MMAB(c, a, b) asm volatile( \
    "mma.sync.aligned.m16n8k16.row.col.f32.bf16.bf16.f32 " \
    "{%0,%1,%2,%3},{%4,%5,%6,%7},{%8,%9},{%0,%1,%2,%3};" \
    : "+f"((c)[0]), "+f"((c)[1]), "+f"((c)[2]), "+f"((c)[3]) \
    : "r"((a).x), "r"((a).y), "r"((a).z), "r"((a).w), "r"((b).x), "r"((b).y))
#define GROUP_BAR(mg) asm volatile("bar.sync %0, %1;" :: "r"(1 + (mg)), "r"(128) : "memory")

// One GRU layer, 24 steps, executed by free-running 128-thread mg-groups.
// Warp w: mg=w&3 (voxels 32mg..32mg+31), ng=w>>2 (j 16ng..16ng+15).
template<bool L0, bool LAST>
static __device__ void layer_run(float* __restrict__ sm, int tid, int blk,
                                 int whO, int wiO, int bsO)
{
    const int lane = tid & 31, w = tid >> 5;
    const int mg = w & 3, ng = w >> 2;
    const int gq = lane >> 2, cc = lane & 3;
    const int vbase = blk * VB;
    const uint2* WHu = (const uint2*)(sm + whO);
    const uint2* WIu = (const uint2*)(sm + wiO);
    const float* BS = sm + bsO;
    float hp[16];
    #pragma unroll
    for (int i = 0; i < 16; ++i) hp[i] = 0.f;

    for (int t = 0; t < TS; ++t) {
        uint4*       hb_n = (uint4*)(sm + ((t & 1) ? S_H0 : S_H1));
        const uint4* hb_c = (const uint4*)(sm + ((t & 1) ? S_H1 : S_H0));

        float cr[4][4], cz[4][4], cnh[4][4], cnx[4][4];
        #pragma unroll
        for (int f = 0; f < 4; ++f)
            #pragma unroll
            for (int q = 0; q < 4; ++q) {
                cr[f][q] = 0.f; cz[f][q] = 0.f; cnh[f][q] = 0.f; cnx[f][q] = 0.f;
            }

        // ---- pass 1: ih MMAs (no h dependency; x straight from global/L2) ----
        if (!L0) {
            const uint4* xs = &g_actb[(size_t)(t * 128 + blk) * 1024];
            #pragma unroll
            for (int kt2 = 0; kt2 < 4; ++kt2) {
                uint2 bi2[6];
                #pragma unroll
                for (int ji = 0; ji < 2; ++ji) {
                    int jt = 2 * ng + ji;
                    bi2[ji*3+0] = WIu[((jt)      * 4 + kt2) * 32 + lane];
                    bi2[ji*3+1] = WIu[((8 + jt)  * 4 + kt2) * 32 + lane];
                    bi2[ji*3+2] = WIu[((16 + jt) * 4 + kt2) * 32 + lane];
                }
                #pragma unroll
                for (int mi = 0; mi < 2; ++mi) {
                    uint4 ax = xs[((2 * mg + mi) * 4 + kt2) * 32 + lane];
                    #pragma unroll
                    for (int ji = 0; ji < 2; ++ji) {
                        int f = mi * 2 + ji;
                        MMAB(cr[f],  ax, bi2[ji*3+0]);
                        MMAB(cz[f],  ax, bi2[ji*3+1]);
                        MMAB(cnx[f], ax, bi2[ji*3+2]);
                    }
                }
            }
        }

        // ---- pass 2: hh MMAs (skipped entirely at t=0) ----
        if (t > 0) {
            #pragma unroll
            for (int kt2 = 0; kt2 < 4; ++kt2) {
                uint2 bh[6];
                #pragma unroll
                for (int ji = 0; ji < 2; ++ji) {
                    int jt = 2 * ng + ji;
                    bh[ji*3+0] = WHu[((jt)      * 4 + kt2) * 32 + lane];
                    bh[ji*3+1] = WHu[((8 + jt)  * 4 + kt2) * 32 + lane];
                    bh[ji*3+2] = WHu[((16 + jt) * 4 + kt2) * 32 + lane];
                }
                #pragma unroll
                for (int mi = 0; mi < 2; ++mi) {
                    uint4 ah = hb_c[((2 * mg + mi) * 4 + kt2) * 32 + lane];
                    #pragma unroll
                    for (int ji = 0; ji < 2; ++ji) {
                        int f = mi * 2 + ji;
                        MMAB(cr[f],  ah, bh[ji*3+0]);
                        MMAB(cz[f],  ah, bh[ji*3+1]);
                        MMAB(cnh[f], ah, bh[ji*3+2]);
                    }
                }
            }
        }

        // ---- thread-local combine; h packs straight into A-frag uint4 ----
        #pragma unroll
        for (int mi = 0; mi < 2; ++mi) {
            int mt = 2 * mg + mi;
            uint32_t rg[4];
            #pragma unroll
            for (int ji = 0; ji < 2; ++ji) {
                int f = mi * 2 + ji;
                float hv[4];
                #pragma unroll
                for (int q = 0; q < 4; ++q) {
                    int j = 16 * ng + 8 * ji + 2 * cc + (q & 1);
                    int v = mt * 16 + gq + 8 * (q >> 1);
                    float xr = 0.f, xz = 0.f, xn;
                    if (L0) {
                        float xv = sm[S_VIN + t * VB + v];
                        xr = xv * sm[S_W0 + j];
                        xz = xv * sm[S_W0 + 64 + j];
                        xn = xv * sm[S_W0 + 128 + j] + BS[192 + j];
                    } else {
                        xn = cnx[f][q] + BS[192 + j];
                    }
                    float r  = sigt(cr[f][q] + xr + BS[j]);
                    float z  = sigt(cz[f][q] + xz + BS[64 + j]);
                    float nn = tanha(xn + r * (cnh[f][q] + BS[128 + j]));
                    float hnv = (1.f - z) * nn + z * hp[f * 4 + q];
                    hp[f * 4 + q] = hnv;
                    hv[q] = hnv;
                    if (LAST)
                        g_act2[((size_t)(t * 64 + j) << 14) + vbase + v] = hnv;
                }
                rg[ji * 2 + 0] = pkbf(hv[0], hv[1]);
                rg[ji * 2 + 1] = pkbf(hv[2], hv[3]);
            }
            uint4 u = make_uint4(rg[0], rg[1], rg[2], rg[3]);
            hb_n[(mt * 4 + ng) * 32 + lane] = u;
            if (!LAST)
                g_actb[(size_t)(t * 128 + blk) * 1024 + (mt * 4 + ng) * 32 + lane] = u;
        }
        GROUP_BAR(mg);   // only this 128-thread group converges
    }
}

__global__ void __launch_bounds__(NT)
fused_rnn_kernel(const float* __restrict__ x,   const int*   __restrict__ lengths,
                 const float* __restrict__ sf,  const float* __restrict__ bp,
                 const float* __restrict__ wih0,const float* __restrict__ whh0,
                 const float* __restrict__ bih0,const float* __restrict__ bhh0,
                 const float* __restrict__ wihL,const float* __restrict__ whhL,
                 const float* __restrict__ bihL,const float* __restrict__ bhhL,
                 const float* __restrict__ bng, const float* __restrict__ bnb,
                 const float* __restrict__ bnm, const float* __restrict__ bnv,
                 const float* __restrict__ fcW, const float* __restrict__ fcb,
                 const float* __restrict__ fcWo,const float* __restrict__ fcbo,
                 float* __restrict__ out)
{
    extern __shared__ float sm[];
    const int tid = threadIdx.x;
    const int blk = blockIdx.x;
    const int vbase = blk * VB;
    const int n  = vbase >> 12;
    const int sb = vbase & 4095;

    // ---- stage ALL layers' weights + biases up front ----
    for (int l = 0; l < 4; ++l) {
        const float* Wh = (l == 0) ? whh0 : whhL + (l - 1) * 12288;
        const float* Wi = (l == 0) ? wih0 : wihL + (l - 1) * 12288;
        const float* Bi = (l == 0) ? bih0 : bihL + (l - 1) * 192;
        const float* Bh = (l == 0) ? bhh0 : bhhL + (l - 1) * 192;
        int whO = (l == 0) ? 0 : (6144 + (l - 1) * 12288);
        uint32_t* WHu = (uint32_t*)(sm + whO);
        uint32_t* WIu = WHu + 6144;
        for (int idx = tid; idx < 6144; idx += NT) {
            int gt = idx >> 8, kt2 = (idx >> 6) & 3, ln = (idx >> 1) & 31, br = idx & 1;
            int g = gt * 8 + (ln >> 2);
            int k = kt2 * 16 + (ln & 3) * 2 + br * 8;
            WHu[idx] = pkbf(Wh[g * 64 + k], Wh[g * 64 + k + 1]);
            if (l > 0) WIu[idx] = pkbf(Wi[g * 64 + k], Wi[g * 64 + k + 1]);
        }
        if (tid < 64) {
            int j = tid;
            sm[S_BS + l * 256 + j]       = Bi[j] + Bh[j];
            sm[S_BS + l * 256 + 64 + j]  = Bi[64 + j] + Bh[64 + j];
            sm[S_BS + l * 256 + 128 + j] = Bh[128 + j];
            sm[S_BS + l * 256 + 192 + j] = Bi[128 + j];
        }
    }
    if (tid < 192) sm[S_W0 + tid] = wih0[tid];
    for (int idx = tid; idx < TS * VB; idx += NT) {   // vin[t][v]
        int t = idx >> 7, v = idx & 127;
        int p = t % 3;
        sm[S_VIN + idx] = x[n * 98304 + t * 4096 + sb + v] * sf[p] + bp[p];
    }
    __syncthreads();

    // ---- four layers, mg-groups free-running throughout ----
    layer_run<true , false>(sm, tid, blk, 0,     0,     S_BS);
    layer_run<false, false>(sm, tid, blk, 6144,  12288, S_BS + 256);
    layer_run<false, false>(sm, tid, blk, 18432, 24576, S_BS + 512);
    layer_run<false, true >(sm, tid, blk, 30720, 36864, S_BS + 768);
    __syncthreads();

    // ---- head: sel = h[len-1]+h[len-4]; 5x (BN+SiLU+FC); BN+SiLU; out ----
    float* A = sm + S_H0;    // [j][v] 64 x 128 (spans H0+H1)
    float* B = sm;           // first 8192 floats of (now dead) weight region
    float* WST = sm + 8192;  // per-iteration fcW staging (4096)
    const int len = lengths[n];
    const int t1 = len - 1, t2 = len - 4;
    #pragma unroll
    for (int it = 0; it < 16; ++it) {
        int idx = tid + it * NT, v = idx & 127, j = idx >> 7;
        A[j * VB + v] = g_act2[((size_t)(t1 * 64 + j) << 14) + vbase + v]
                      + g_act2[((size_t)(t2 * 64 + j) << 14) + vbase + v];
    }
    __syncthreads();
    for (int i = 0; i < 5; ++i) {
        for (int idx = tid; idx < 4096; idx += NT) WST[idx] = fcW[i * 4096 + idx];
        #pragma unroll
        for (int it = 0; it < 16; ++it) {
            int idx = tid + it * NT, v = idx & 127, j = idx >> 7;
            float y = bng[i * 64 + j] * (A[j * VB + v] - bnm[i * 64 + j])
                      * rsqrtf(bnv[i * 64 + j] + 1e-5f) + bnb[i * 64 + j];
            A[j * VB + v] = y * sigt(y);
        }
        __syncthreads();
        #pragma unroll
        for (int it = 0; it < 16; ++it) {
            int idx = tid + it * NT, v = idx & 127, o = idx >> 7;
            float acc = fcb[i * 64 + o];
            #pragma unroll 8
            for (int j = 0; j < 64; ++j) acc += A[j * VB + v] * WST[o * 64 + j];
            B[o * VB + v] = acc;
        }
        __syncthreads();
        float* tswp = A; A = B; B = tswp;
    }
    #pragma unroll
    for (int it = 0; it < 16; ++it) {
        int idx = tid + it * NT, v = idx & 127, j = idx >> 7;
        float y = bng[5 * 64 + j] * (A[j * VB + v] - bnm[5 * 64 + j])
                  * rsqrtf(bnv[5 * 64 + j] + 1e-5f) + bnb[5 * 64 + j];
        A[j * VB + v] = y * sigt(y);
    }
    __syncthreads();
    if (tid < VB) {
        float acc = fcbo[0];
        #pragma unroll 8
        for (int j = 0; j < 64; ++j) acc += A[j * VB + tid] * fcWo[j];
        out[vbase + tid] = acc;
    }
}

extern "C" void kernel_launch(void* const* d_in, const int* in_sizes, int n_in,
                              void* d_out, int out_size)
{
    const float* x     = (const float*)d_in[0];
    const int*   lens  = (const int*)  d_in[1];
    const float* sf    = (const float*)d_in[2];
    const float* bp    = (const float*)d_in[3];
    const float* wih0  = (const float*)d_in[4];
    const float* whh0  = (const float*)d_in[5];
    const float* bih0  = (const float*)d_in[6];
    const float* bhh0  = (const float*)d_in[7];
    const float* wihL  = (const float*)d_in[8];
    const float* whhL  = (const float*)d_in[9];
    const float* bihL  = (const float*)d_in[10];
    const float* bhhL  = (const float*)d_in[11];
    const float* bng   = (const float*)d_in[12];
    const float* bnb   = (const float*)d_in[13];
    const float* bnm   = (const float*)d_in[14];
    const float* bnv   = (const float*)d_in[15];
    const float* fcW   = (const float*)d_in[16];
    const float* fcb   = (const float*)d_in[17];
    const float* fcWo  = (const float*)d_in[18];
    const float* fcbo  = (const float*)d_in[19];
    float* out = (float*)d_out;

    const size_t smem = SMEM_FLOATS * sizeof(float);   // 221,952 B
    cudaFuncSetAttribute(fused_rnn_kernel,
                         cudaFuncAttributeMaxDynamicSharedMemorySize, (int)smem);
    fused_rnn_kernel<<<128, NT, smem>>>(
        x, lens, sf, bp, wih0, whh0, bih0, bhh0,
        wihL, whhL, bihL, bhhL, bng, bnb, bnm, bnv,
        fcW, fcb, fcWo, fcbo, out);
}